// round 11
// baseline (speedup 1.0000x reference)
#include <cuda_runtime.h>
#include <cstdint>
#include <math.h>

#define WTOT 4096
#define CHUNK2 128
#define HDIM 128
#define BATCH 64
#define NCH2 (WTOT / CHUNK2)   // 32 chunks of 128 rows

__device__ __align__(16) float g_pvec[BATCH * NCH2 * HDIM];  // 1 MB partials
__device__ __align__(16) float g_psum[BATCH * NCH2];

__device__ __forceinline__ float warp_sum(float p) {
    #pragma unroll
    for (int o = 16; o > 0; o >>= 1) p += __shfl_down_sync(0xffffffffu, p, o);
    return p;
}

__device__ __forceinline__ float sigmoidf_(float x) {
    return 1.0f / (1.0f + expf(-x));
}

__device__ __forceinline__ float dot4(float4 a, float4 b) {
    return a.x * b.x + a.y * b.y + a.z * b.z + a.w * b.w;
}

__device__ __forceinline__ void cp16(void* smem_dst, const void* gmem_src) {
    unsigned int s = (unsigned int)__cvta_generic_to_shared(smem_dst);
    asm volatile("cp.async.cg.shared.global [%0], [%1], 16;" :: "r"(s), "l"(gmem_src));
}
#define CP_COMMIT() asm volatile("cp.async.commit_group;")
#define CP_WAIT(n)  asm volatile("cp.async.wait_group %0;" :: "n"(n))
#define BAR_HALF()  asm volatile("bar.sync 1, 512;" ::: "memory")

// ---------------------------------------------------------------------------
// Attention kernel: 2048 blocks x 256 threads, 128-row tiles staged by
// cp.async into 64KB dynamic smem. No register-resident tile, no pre blocks.
// ---------------------------------------------------------------------------
__device__ __forceinline__ void score_rows8(
    const float* tile, float4 wv, float bias, float* s_sh,
    int base, int wrp, int lane)
{
    float acc[8];
    #pragma unroll
    for (int t = 0; t < 8; t++) {
        const float4 rv = *(const float4*)&tile[(base + wrp + 8 * t) * HDIM + lane * 4];
        acc[t] = dot4(rv, wv);
    }
    #pragma unroll
    for (int o = 16; o > 0; o >>= 1) {
        #pragma unroll
        for (int t = 0; t < 8; t++)
            acc[t] += __shfl_down_sync(0xffffffffu, acc[t], o);
    }
    if (lane == 0) {
        #pragma unroll
        for (int t = 0; t < 8; t++)
            s_sh[base + wrp + 8 * t] = acc[t] + bias;
    }
}

__global__ void __launch_bounds__(256) attn_kernel(
    const float* __restrict__ enc,
    const float* __restrict__ h0,
    const float* __restrict__ c0,
    const float* __restrict__ attW,
    const float* __restrict__ attb)
{
    extern __shared__ __align__(16) float tile[];   // 128*128 floats = 64 KB

    __shared__ float s_sh[CHUNK2];
    __shared__ float e_sh[CHUNK2];
    __shared__ float red[4];
    __shared__ float bias_sh;
    __shared__ float sprev_sh;
    __shared__ float part2[2][HDIM];

    const int tid   = threadIdx.x;
    const int lane  = tid & 31;
    const int wrp   = tid >> 5;
    const int chunk = blockIdx.x & (NCH2 - 1);
    const int b     = blockIdx.x >> 5;
    const int start = chunk * CHUNK2;

    // Stage the 128x128 tile: 4096 float4, 16 per thread, 2 commit groups.
    {
        const float4* src = (const float4*)(enc + ((size_t)b * WTOT + start) * HDIM);
        float4* dst = (float4*)tile;
        #pragma unroll
        for (int i = 0; i < 8; i++) cp16(&dst[tid + 256 * i], &src[tid + 256 * i]);
        CP_COMMIT();
        #pragma unroll
        for (int i = 8; i < 16; i++) cp16(&dst[tid + 256 * i], &src[tid + 256 * i]);
        CP_COMMIT();
    }

    // Prev-row load + bias compute overlap the transfers.
    float4 vprev = make_float4(0.f, 0.f, 0.f, 0.f);
    if (wrp == 0 && start > 0)
        vprev = ((const float4*)(enc + ((size_t)b * WTOT + start - 1) * HDIM))[lane];
    const float4 wv = ((const float4*)attW)[lane];

    if (tid < HDIM) {
        float p = h0[BATCH * HDIM + b * HDIM + tid]
                * c0[BATCH * HDIM + b * HDIM + tid]
                * attW[HDIM + tid];
        p = warp_sum(p);
        if (lane == 0) red[wrp] = p;
    }
    __syncthreads();
    if (tid == 0) bias_sh = red[0] + red[1] + red[2] + red[3] + attb[0];

    CP_WAIT(1);
    __syncthreads();          // rows 0..63 visible; bias_sh published
    const float bias = bias_sh;

    // Scores rows 0..63 (overlaps second-half transfer)
    score_rows8(tile, wv, bias, s_sh, 0, wrp, lane);
    if (wrp == 0 && start > 0) {
        float s = warp_sum(dot4(vprev, wv));
        if (lane == 0) sprev_sh = s + bias;
    }

    CP_WAIT(0);
    __syncthreads();          // rows 64..127 visible
    score_rows8(tile, wv, bias, s_sh, 64, wrp, lane);
    __syncthreads();

    if (tid < CHUNK2) {
        float logit;
        if (tid == 0) logit = (start == 0) ? 0.0f : sprev_sh;
        else          logit = s_sh[tid - 1];
        e_sh[tid] = expf(logit);
    }
    __syncthreads();

    // Weighted partial sum: 2 row-groups x 128 h-columns.
    {
        const int h = tid & 127, grp = tid >> 7;
        float acc = 0.0f;
        #pragma unroll
        for (int j = 0; j < 64; j++) {
            const int r = grp * 64 + j;
            acc += e_sh[r] * tile[r * HDIM + h];
        }
        part2[grp][h] = acc;
    }
    __syncthreads();
    if (tid < HDIM)
        g_pvec[((size_t)b * NCH2 + chunk) * HDIM + tid] = part2[0][tid] + part2[1][tid];
    if (wrp == 0) {
        float es = e_sh[lane] + e_sh[lane + 32] + e_sh[lane + 64] + e_sh[lane + 96];
        es = warp_sum(es);
        if (lane == 0) g_psum[b * NCH2 + chunk] = es;
    }
}

// ---------------------------------------------------------------------------
// Pipelined coalesced warp-dots: 16 gates per warp, K=128 (layer weights).
// ---------------------------------------------------------------------------
__device__ __forceinline__ void lstm_gates(
    const float* __restrict__ W, const float4 xv,
    const float* __restrict__ pre_sh, float* gate_sh,
    int wrp, int lane)
{
    const int kbase = wrp * 16;
    float4 w[2][4];
    #pragma unroll
    for (int t = 0; t < 4; t++)
        w[0][t] = ((const float4*)(W + (kbase + t) * HDIM))[lane];
    #pragma unroll
    for (int g = 0; g < 4; g++) {
        if (g < 3) {
            #pragma unroll
            for (int t = 0; t < 4; t++)
                w[(g + 1) & 1][t] =
                    ((const float4*)(W + (kbase + (g + 1) * 4 + t) * HDIM))[lane];
        }
        float acc[4];
        #pragma unroll
        for (int t = 0; t < 4; t++) acc[t] = dot4(w[g & 1][t], xv);
        #pragma unroll
        for (int o = 16; o > 0; o >>= 1) {
            #pragma unroll
            for (int t = 0; t < 4; t++)
                acc[t] += __shfl_down_sync(0xffffffffu, acc[t], o);
        }
        if (lane == 0) {
            #pragma unroll
            for (int t = 0; t < 4; t++) {
                const int k = kbase + g * 4 + t;
                gate_sh[k] = acc[t] + pre_sh[k];
            }
        }
    }
}

// hh-gate precompute on dedicated warps: 32 gates/warp/layer, K=128.
__device__ __forceinline__ void pre_gates(
    const float* __restrict__ Whh, const float4 hv,
    const float* __restrict__ bih, const float* __restrict__ bhh,
    float* pre_sh, int wloc, int lane)
{
    const int kbase = wloc * 32;
    float4 w[2][4];
    #pragma unroll
    for (int t = 0; t < 4; t++)
        w[0][t] = ((const float4*)(Whh + (kbase + t) * HDIM))[lane];
    #pragma unroll
    for (int g = 0; g < 8; g++) {
        if (g < 7) {
            #pragma unroll
            for (int t = 0; t < 4; t++)
                w[(g + 1) & 1][t] =
                    ((const float4*)(Whh + (kbase + (g + 1) * 4 + t) * HDIM))[lane];
        }
        float acc[4];
        #pragma unroll
        for (int t = 0; t < 4; t++) acc[t] = dot4(w[g & 1][t], hv);
        #pragma unroll
        for (int o = 16; o > 0; o >>= 1) {
            #pragma unroll
            for (int t = 0; t < 4; t++)
                acc[t] += __shfl_down_sync(0xffffffffu, acc[t], o);
        }
        if (lane == 0) {
            #pragma unroll
            for (int t = 0; t < 4; t++) {
                const int k = kbase + g * 4 + t;
                pre_sh[k] = acc[t] + bih[k] + bhh[k];
            }
        }
    }
}

// ---------------------------------------------------------------------------
// Decode: warps 0-15 stage0+xin; warps 16-31 hh precompute; join for LSTM.
// ---------------------------------------------------------------------------
__global__ void __launch_bounds__(1024) decode_kernel(
    const float* __restrict__ input,
    const float* __restrict__ h0,
    const float* __restrict__ c0,
    const float* __restrict__ inp_W, const float* __restrict__ inp_b,
    const float* __restrict__ W_ih0, const float* __restrict__ W_hh0,
    const float* __restrict__ b_ih0, const float* __restrict__ b_hh0,
    const float* __restrict__ W_ih1, const float* __restrict__ W_hh1,
    const float* __restrict__ b_ih1, const float* __restrict__ b_hh1,
    float* __restrict__ out)
{
    __shared__ __align__(16) float cat_sh[256];
    __shared__ __align__(16) float xin_sh[HDIM];
    __shared__ __align__(16) float h1_sh[HDIM];
    __shared__ float gate_sh[512];
    __shared__ float c0_sh[2 * HDIM];
    __shared__ float vred[4][HDIM];
    __shared__ float sarr[NCH2];
    __shared__ float pre0_sh[512];
    __shared__ float pre1_sh[512];
    __shared__ float S_sh;

    const int b = blockIdx.x;
    const int tid = threadIdx.x, lane = tid & 31, wrp = tid >> 5;

    if (wrp >= 16) {
        // ---- precompute warps: hh gate halves for both layers ----
        const int wloc = wrp - 16;
        const float4 hv0 = ((const float4*)(h0 + b * HDIM))[lane];
        const float4 hv1 = ((const float4*)(h0 + BATCH * HDIM + b * HDIM))[lane];
        pre_gates(W_hh0, hv0, b_ih0, b_hh0, pre0_sh, wloc, lane);
        pre_gates(W_hh1, hv1, b_ih1, b_hh1, pre1_sh, wloc, lane);
    } else {
        // ---- stage0 + xin warps (512 threads, named barrier 1) ----
        if (tid < HDIM) {
            c0_sh[tid]        = c0[b * HDIM + tid];
            c0_sh[HDIM + tid] = c0[BATCH * HDIM + b * HDIM + tid];
        }
        if (tid < NCH2) sarr[tid] = g_psum[b * NCH2 + tid];
        {
            const int h = tid & 127, grp = tid >> 7;   // 4 groups x 8 chunks
            float v = 0.0f;
            #pragma unroll
            for (int c = 0; c < 8; c++)
                v += g_pvec[((size_t)b * NCH2 + grp * 8 + c) * HDIM + h];
            vred[grp][h] = v;
        }
        BAR_HALF();
        float vcol = 0.0f;
        if (tid < HDIM) {
            #pragma unroll
            for (int g = 0; g < 4; g++) vcol += vred[g][tid];
        }
        if (wrp == 0) {
            float s = warp_sum(sarr[lane]);
            if (lane == 0) S_sh = s;
        }
        BAR_HALF();
        if (tid < HDIM) {
            cat_sh[tid]        = vcol / S_sh;
            cat_sh[HDIM + tid] = input[b * HDIM + tid];
        }
        BAR_HALF();

        // xin: 16 warps x 8 outputs, K=256, two groups of 4
        {
            const float4 c0v = ((const float4*)cat_sh)[lane];
            const float4 c1v = ((const float4*)cat_sh)[lane + 32];
            #pragma unroll
            for (int g = 0; g < 2; g++) {
                float4 a0[4], a1[4];
                #pragma unroll
                for (int t = 0; t < 4; t++) {
                    const float4* wr = (const float4*)(inp_W + (wrp * 8 + g * 4 + t) * 256);
                    a0[t] = wr[lane];
                    a1[t] = wr[lane + 32];
                }
                float acc[4];
                #pragma unroll
                for (int t = 0; t < 4; t++)
                    acc[t] = dot4(a0[t], c0v) + dot4(a1[t], c1v);
                #pragma unroll
                for (int o = 16; o > 0; o >>= 1) {
                    #pragma unroll
                    for (int t = 0; t < 4; t++)
                        acc[t] += __shfl_down_sync(0xffffffffu, acc[t], o);
                }
                if (lane == 0) {
                    #pragma unroll
                    for (int t = 0; t < 4; t++) {
                        const int i = wrp * 8 + g * 4 + t;
                        xin_sh[i] = acc[t] + inp_b[i];
                    }
                }
            }
        }
    }
    __syncthreads();    // join: xin_sh, pre0_sh, pre1_sh, c0_sh all ready

    float* out_h1 = out + 8192 + b * HDIM;
    float* out_h2 = out + 16384 + b * HDIM;
    float* out_c1 = out + 24576 + b * HDIM;
    float* out_c2 = out + 32768 + b * HDIM;
    float* out_y  = out + b * HDIM;

    // LSTM layer 0
    lstm_gates(W_ih0, ((const float4*)xin_sh)[lane], pre0_sh, gate_sh, wrp, lane);
    __syncthreads();
    if (tid < HDIM) {
        const float ig = gate_sh[tid];
        const float fg = gate_sh[128 + tid];
        const float gg = gate_sh[256 + tid];
        const float og = gate_sh[384 + tid];
        const float cn = sigmoidf_(fg) * c0_sh[tid] + sigmoidf_(ig) * tanhf(gg);
        const float hn = sigmoidf_(og) * tanhf(cn);
        h1_sh[tid]  = hn;
        out_c1[tid] = cn;
        out_h1[tid] = hn;
    }
    __syncthreads();

    // LSTM layer 1
    lstm_gates(W_ih1, ((const float4*)h1_sh)[lane], pre1_sh, gate_sh, wrp, lane);
    __syncthreads();
    if (tid < HDIM) {
        const float ig = gate_sh[tid];
        const float fg = gate_sh[128 + tid];
        const float gg = gate_sh[256 + tid];
        const float og = gate_sh[384 + tid];
        const float cn = sigmoidf_(fg) * c0_sh[HDIM + tid] + sigmoidf_(ig) * tanhf(gg);
        const float hn = sigmoidf_(og) * tanhf(cn);
        out_c2[tid] = cn;
        out_h2[tid] = hn;
        out_y[tid]  = hn;
    }
}

extern "C" void kernel_launch(void* const* d_in, const int* in_sizes, int n_in,
                              void* d_out, int out_size)
{
    const float* input  = (const float*)d_in[0];
    const float* h0     = (const float*)d_in[1];
    const float* c0     = (const float*)d_in[2];
    const float* enc    = (const float*)d_in[3];
    const float* attW   = (const float*)d_in[4];
    const float* attb   = (const float*)d_in[5];
    const float* inp_W  = (const float*)d_in[6];
    const float* inp_b  = (const float*)d_in[7];
    const float* W_ih0  = (const float*)d_in[8];
    const float* W_hh0  = (const float*)d_in[9];
    const float* b_ih0  = (const float*)d_in[10];
    const float* b_hh0  = (const float*)d_in[11];
    const float* W_ih1  = (const float*)d_in[12];
    const float* W_hh1  = (const float*)d_in[13];
    const float* b_ih1  = (const float*)d_in[14];
    const float* b_hh1  = (const float*)d_in[15];
    float* out = (float*)d_out;

    const int tile_bytes = CHUNK2 * HDIM * sizeof(float);   // 64 KB
    cudaFuncSetAttribute(attn_kernel,
                         cudaFuncAttributeMaxDynamicSharedMemorySize, tile_bytes);

    attn_kernel<<<NCH2 * BATCH, 256, tile_bytes>>>(enc, h0, c0, attW, attb);
    decode_kernel<<<BATCH, 1024>>>(input, h0, c0, inp_W, inp_b,
                                   W_ih0, W_hh0, b_ih0, b_hh0,
                                   W_ih1, W_hh1, b_ih1, b_hh1, out);
}

// round 13
// speedup vs baseline: 1.0498x; 1.0498x over previous
#include <cuda_runtime.h>
#include <cstdint>
#include <math.h>

#define WTOT 4096
#define CHUNK2 128
#define HDIM 128
#define BATCH 64
#define NCH2 (WTOT / CHUNK2)   // 32 chunks of 128 rows
#define NATT (NCH2 * BATCH)    // 2048 attention blocks
#define NPRE 512               // pre blocks appended after attention blocks

__device__ __align__(16) float g_pvec[BATCH * NCH2 * HDIM];
__device__ __align__(16) float g_psum[BATCH * NCH2];
__device__ __align__(16) float g_pre0[BATCH * 512];
__device__ __align__(16) float g_pre1[BATCH * 512];

__device__ __forceinline__ float warp_sum(float p) {
    #pragma unroll
    for (int o = 16; o > 0; o >>= 1) p += __shfl_down_sync(0xffffffffu, p, o);
    return p;
}

__device__ __forceinline__ float sigmoidf_(float x) {
    return 1.0f / (1.0f + expf(-x));
}

__device__ __forceinline__ float dot4(float4 a, float4 b) {
    return a.x * b.x + a.y * b.y + a.z * b.z + a.w * b.w;
}

__device__ __forceinline__ void cp16(void* smem_dst, const void* gmem_src) {
    unsigned int s = (unsigned int)__cvta_generic_to_shared(smem_dst);
    asm volatile("cp.async.cg.shared.global [%0], [%1], 16;" :: "r"(s), "l"(gmem_src));
}
#define CP_COMMIT() asm volatile("cp.async.commit_group;")
#define CP_WAIT(n)  asm volatile("cp.async.wait_group %0;" :: "n"(n))

// ---------------------------------------------------------------------------
// score 64 rows (base..base+63): 8 warps x 8 rows, interleaved shfl chains
// ---------------------------------------------------------------------------
__device__ __forceinline__ void score_rows8(
    const float* tile, float4 wv, float bias, float* s_sh,
    int base, int wrp, int lane)
{
    float acc[8];
    #pragma unroll
    for (int t = 0; t < 8; t++) {
        const float4 rv = *(const float4*)&tile[(base + wrp + 8 * t) * HDIM + lane * 4];
        acc[t] = dot4(rv, wv);
    }
    #pragma unroll
    for (int o = 16; o > 0; o >>= 1) {
        #pragma unroll
        for (int t = 0; t < 8; t++)
            acc[t] += __shfl_down_sync(0xffffffffu, acc[t], o);
    }
    if (lane == 0) {
        #pragma unroll
        for (int t = 0; t < 8; t++)
            s_sh[base + wrp + 8 * t] = acc[t] + bias;
    }
}

// ---------------------------------------------------------------------------
// Attention (+ tail pre) kernel. Blocks [0, NATT): 128-row tiles, two 64-row
// subtiles pipelined (A's compute overlaps B's cp.async). Blocks >= NATT:
// hh-gate precompute filling the tail wave.
// ---------------------------------------------------------------------------
__global__ void __launch_bounds__(256) attn_pre_kernel(
    const float* __restrict__ enc,
    const float* __restrict__ h0,
    const float* __restrict__ c0,
    const float* __restrict__ attW,
    const float* __restrict__ attb,
    const float* __restrict__ W_hh0,
    const float* __restrict__ b_ih0, const float* __restrict__ b_hh0,
    const float* __restrict__ W_hh1,
    const float* __restrict__ b_ih1, const float* __restrict__ b_hh1)
{
    const int tid  = threadIdx.x;
    const int lane = tid & 31;
    const int wrp  = tid >> 5;

    if (blockIdx.x >= NATT) {
        // ---- tail pre block: b = p>>3, gate group (p&7)*64 ----
        const int p  = blockIdx.x - NATT;
        const int b  = p >> 3;
        const int k0 = (p & 7) * 64;
        const float4 hv0 = ((const float4*)(h0 + b * HDIM))[lane];
        const float4 hv1 = ((const float4*)(h0 + BATCH * HDIM + b * HDIM))[lane];
        #pragma unroll 4
        for (int t = 0; t < 8; t++) {
            const int k = k0 + wrp * 8 + t;
            float p0 = dot4(((const float4*)(W_hh0 + k * HDIM))[lane], hv0);
            p0 = warp_sum(p0);
            if (lane == 0) g_pre0[b * 512 + k] = p0 + b_ih0[k] + b_hh0[k];
        }
        #pragma unroll 4
        for (int t = 0; t < 8; t++) {
            const int k = k0 + wrp * 8 + t;
            float p1 = dot4(((const float4*)(W_hh1 + k * HDIM))[lane], hv1);
            p1 = warp_sum(p1);
            if (lane == 0) g_pre1[b * 512 + k] = p1 + b_ih1[k] + b_hh1[k];
        }
        return;
    }

    extern __shared__ __align__(16) float tile[];   // 128*128 floats = 64 KB

    __shared__ float s_sh[CHUNK2];
    __shared__ float e_sh[CHUNK2];
    __shared__ float red[4];
    __shared__ float bias_sh;
    __shared__ float sprev_sh;
    __shared__ float part2[2][HDIM];

    const int chunk = blockIdx.x & (NCH2 - 1);
    const int b     = blockIdx.x >> 5;
    const int start = chunk * CHUNK2;

    // Stage both 64-row subtiles: 2 commit groups of 8 float4 per thread.
    {
        const float4* src = (const float4*)(enc + ((size_t)b * WTOT + start) * HDIM);
        float4* dst = (float4*)tile;
        #pragma unroll
        for (int i = 0; i < 8; i++) cp16(&dst[tid + 256 * i], &src[tid + 256 * i]);
        CP_COMMIT();
        #pragma unroll
        for (int i = 8; i < 16; i++) cp16(&dst[tid + 256 * i], &src[tid + 256 * i]);
        CP_COMMIT();
    }

    float4 vprev = make_float4(0.f, 0.f, 0.f, 0.f);
    if (wrp == 0 && start > 0)
        vprev = ((const float4*)(enc + ((size_t)b * WTOT + start - 1) * HDIM))[lane];
    const float4 wv = ((const float4*)attW)[lane];

    // Bias compute overlaps the transfers.
    if (tid < HDIM) {
        float p = h0[BATCH * HDIM + b * HDIM + tid]
                * c0[BATCH * HDIM + b * HDIM + tid]
                * attW[HDIM + tid];
        p = warp_sum(p);
        if (lane == 0) red[wrp] = p;
    }
    __syncthreads();
    if (tid == 0) bias_sh = red[0] + red[1] + red[2] + red[3] + attb[0];

    CP_WAIT(1);
    __syncthreads();          // subtile A visible; bias published
    const float bias = bias_sh;

    // --- Subtile A: score -> exp -> weighted sum (B still loading) ---
    score_rows8(tile, wv, bias, s_sh, 0, wrp, lane);
    if (wrp == 0 && start > 0) {
        float s = warp_sum(dot4(vprev, wv));
        if (lane == 0) sprev_sh = s + bias;
    }
    __syncthreads();
    if (tid < 64) {
        float logit;
        if (tid == 0) logit = (start == 0) ? 0.0f : sprev_sh;
        else          logit = s_sh[tid - 1];
        e_sh[tid] = expf(logit);
    }
    __syncthreads();

    const int h = tid & 127, grp = tid >> 7;
    float acc_v = 0.0f;
    {
        #pragma unroll
        for (int j = 0; j < 32; j++) {
            const int r = grp * 32 + j;
            acc_v += e_sh[r] * tile[r * HDIM + h];
        }
    }

    CP_WAIT(0);
    __syncthreads();          // subtile B visible

    // --- Subtile B: score -> exp -> weighted sum ---
    score_rows8(tile, wv, bias, s_sh, 64, wrp, lane);
    __syncthreads();
    if (tid < 64) {
        const int r = 64 + tid;
        e_sh[r] = expf(s_sh[r - 1]);
    }
    __syncthreads();
    {
        #pragma unroll
        for (int j = 0; j < 32; j++) {
            const int r = 64 + grp * 32 + j;
            acc_v += e_sh[r] * tile[r * HDIM + h];
        }
    }
    part2[grp][h] = acc_v;
    __syncthreads();
    if (tid < HDIM)
        g_pvec[((size_t)b * NCH2 + chunk) * HDIM + tid] = part2[0][tid] + part2[1][tid];
    if (wrp == 0) {
        float es = e_sh[lane] + e_sh[lane + 32] + e_sh[lane + 64] + e_sh[lane + 96];
        es = warp_sum(es);
        if (lane == 0) g_psum[b * NCH2 + chunk] = es;
    }
}

// ---------------------------------------------------------------------------
// Pipelined coalesced warp-dots: 16 gates per warp, K=128.
// ---------------------------------------------------------------------------
__device__ __forceinline__ void lstm_gates(
    const float* __restrict__ W, const float4 xv,
    const float* __restrict__ pre_sh, float* gate_sh,
    int wrp, int lane)
{
    const int kbase = wrp * 16;
    float4 w[2][4];
    #pragma unroll
    for (int t = 0; t < 4; t++)
        w[0][t] = ((const float4*)(W + (kbase + t) * HDIM))[lane];
    #pragma unroll
    for (int g = 0; g < 4; g++) {
        if (g < 3) {
            #pragma unroll
            for (int t = 0; t < 4; t++)
                w[(g + 1) & 1][t] =
                    ((const float4*)(W + (kbase + (g + 1) * 4 + t) * HDIM))[lane];
        }
        float acc[4];
        #pragma unroll
        for (int t = 0; t < 4; t++) acc[t] = dot4(w[g & 1][t], xv);
        #pragma unroll
        for (int o = 16; o > 0; o >>= 1) {
            #pragma unroll
            for (int t = 0; t < 4; t++)
                acc[t] += __shfl_down_sync(0xffffffffu, acc[t], o);
        }
        if (lane == 0) {
            #pragma unroll
            for (int t = 0; t < 4; t++) {
                const int k = kbase + g * 4 + t;
                gate_sh[k] = acc[t] + pre_sh[k];
            }
        }
    }
}

// ---------------------------------------------------------------------------
// Decode (R9 layout): one block per batch, 1024 threads, pre from gmem.
// ---------------------------------------------------------------------------
__global__ void __launch_bounds__(1024) decode_kernel(
    const float* __restrict__ input,
    const float* __restrict__ c0,
    const float* __restrict__ inp_W, const float* __restrict__ inp_b,
    const float* __restrict__ W_ih0,
    const float* __restrict__ W_ih1,
    float* __restrict__ out)
{
    __shared__ __align__(16) float cat_sh[256];
    __shared__ __align__(16) float xin_sh[HDIM];
    __shared__ __align__(16) float h1_sh[HDIM];
    __shared__ float gate_sh[512];
    __shared__ float c0_sh[2 * HDIM];
    __shared__ float vred[4][HDIM];
    __shared__ float sarr[NCH2];
    __shared__ float pre0_sh[512];
    __shared__ float pre1_sh[512];
    __shared__ float S_sh;

    const int b = blockIdx.x;
    const int tid = threadIdx.x, lane = tid & 31, wrp = tid >> 5;

    // Early independent loads
    if (tid < HDIM) {
        c0_sh[tid]        = c0[b * HDIM + tid];
        c0_sh[HDIM + tid] = c0[BATCH * HDIM + b * HDIM + tid];
    }
    if (tid < 512) pre0_sh[tid] = g_pre0[b * 512 + tid];
    else           pre1_sh[tid - 512] = g_pre1[b * 512 + (tid - 512)];

    // Stage 0: reduce attention partials (32 chunks)
    if (tid < NCH2) sarr[tid] = g_psum[b * NCH2 + tid];
    {
        const int h = tid & 127, grp = (tid >> 7) & 3;  // 4 groups x 8 chunks
        float v = 0.0f;
        #pragma unroll
        for (int c = 0; c < 8; c++)
            v += g_pvec[((size_t)b * NCH2 + grp * 8 + c) * HDIM + h];
        if (tid < 512) vred[grp][h] = v;
        else           vred[grp][h] += 0.0f;   // upper half contributes below
    }
    // NOTE: with 1024 threads, tid>=512 duplicates grp 0..3 — serialize safely:
    __syncthreads();
    if (tid >= 512) {
        const int h = tid & 127, grp = (tid >> 7) & 3;
        (void)h; (void)grp;
    }
    float vcol = 0.0f;
    if (tid < HDIM) {
        #pragma unroll
        for (int g = 0; g < 4; g++) vcol += vred[g][tid];
    }
    if (wrp == 0) {
        float s = warp_sum(sarr[lane]);
        if (lane == 0) S_sh = s;
    }
    __syncthreads();
    if (tid < HDIM) {
        cat_sh[tid]        = vcol / S_sh;
        cat_sh[HDIM + tid] = input[b * HDIM + tid];
    }
    __syncthreads();

    // xin: 32 warps x 4 outputs, K=256. Prefetch weights then 4 chains.
    {
        const float4 c0v = ((const float4*)cat_sh)[lane];
        const float4 c1v = ((const float4*)cat_sh)[lane + 32];
        float4 a0[4], a1[4];
        #pragma unroll
        for (int t = 0; t < 4; t++) {
            const float4* wrow = (const float4*)(inp_W + (wrp * 4 + t) * 256);
            a0[t] = wrow[lane];
            a1[t] = wrow[lane + 32];
        }
        float acc[4];
        #pragma unroll
        for (int t = 0; t < 4; t++)
            acc[t] = dot4(a0[t], c0v) + dot4(a1[t], c1v);
        #pragma unroll
        for (int o = 16; o > 0; o >>= 1) {
            #pragma unroll
            for (int t = 0; t < 4; t++)
                acc[t] += __shfl_down_sync(0xffffffffu, acc[t], o);
        }
        if (lane == 0) {
            #pragma unroll
            for (int t = 0; t < 4; t++) {
                const int i = wrp * 4 + t;
                xin_sh[i] = acc[t] + inp_b[i];
            }
        }
    }
    __syncthreads();

    float* out_h1 = out + 8192 + b * HDIM;
    float* out_h2 = out + 16384 + b * HDIM;
    float* out_c1 = out + 24576 + b * HDIM;
    float* out_c2 = out + 32768 + b * HDIM;
    float* out_y  = out + b * HDIM;

    // LSTM layer 0
    lstm_gates(W_ih0, ((const float4*)xin_sh)[lane], pre0_sh, gate_sh, wrp, lane);
    __syncthreads();
    if (tid < HDIM) {
        const float ig = gate_sh[tid];
        const float fg = gate_sh[128 + tid];
        const float gg = gate_sh[256 + tid];
        const float og = gate_sh[384 + tid];
        const float cn = sigmoidf_(fg) * c0_sh[tid] + sigmoidf_(ig) * tanhf(gg);
        const float hn = sigmoidf_(og) * tanhf(cn);
        h1_sh[tid]  = hn;
        out_c1[tid] = cn;
        out_h1[tid] = hn;
    }
    __syncthreads();

    // LSTM layer 1
    lstm_gates(W_ih1, ((const float4*)h1_sh)[lane], pre1_sh, gate_sh, wrp, lane);
    __syncthreads();
    if (tid < HDIM) {
        const float ig = gate_sh[tid];
        const float fg = gate_sh[128 + tid];
        const float gg = gate_sh[256 + tid];
        const float og = gate_sh[384 + tid];
        const float cn = sigmoidf_(fg) * c0_sh[HDIM + tid] + sigmoidf_(ig) * tanhf(gg);
        const float hn = sigmoidf_(og) * tanhf(cn);
        out_c2[tid] = cn;
        out_h2[tid] = hn;
        out_y[tid]  = hn;
    }
}

extern "C" void kernel_launch(void* const* d_in, const int* in_sizes, int n_in,
                              void* d_out, int out_size)
{
    const float* input  = (const float*)d_in[0];
    const float* h0     = (const float*)d_in[1];
    const float* c0     = (const float*)d_in[2];
    const float* enc    = (const float*)d_in[3];
    const float* attW   = (const float*)d_in[4];
    const float* attb   = (const float*)d_in[5];
    const float* inp_W  = (const float*)d_in[6];
    const float* inp_b  = (const float*)d_in[7];
    const float* W_ih0  = (const float*)d_in[8];
    const float* W_hh0  = (const float*)d_in[9];
    const float* b_ih0  = (const float*)d_in[10];
    const float* b_hh0  = (const float*)d_in[11];
    const float* W_ih1  = (const float*)d_in[12];
    const float* W_hh1  = (const float*)d_in[13];
    const float* b_ih1  = (const float*)d_in[14];
    const float* b_hh1  = (const float*)d_in[15];
    float* out = (float*)d_out;

    const int tile_bytes = CHUNK2 * HDIM * sizeof(float);   // 64 KB
    cudaFuncSetAttribute(attn_pre_kernel,
                         cudaFuncAttributeMaxDynamicSharedMemorySize, tile_bytes);

    attn_pre_kernel<<<NATT + NPRE, 256, tile_bytes>>>(
        enc, h0, c0, attW, attb,
        W_hh0, b_ih0, b_hh0, W_hh1, b_ih1, b_hh1);
    decode_kernel<<<BATCH, 1024>>>(input, c0, inp_W, inp_b, W_ih0, W_ih1, out);
}

// round 14
// speedup vs baseline: 1.0916x; 1.0399x over previous
#include <cuda_runtime.h>
#include <cstdint>
#include <math.h>

#define WTOT 4096
#define CHUNK 64
#define HDIM 128
#define BATCH 64
#define NCH (WTOT / CHUNK)      // 64 chunks of 64 rows
#define NATT (NCH * BATCH)      // 4096 attention blocks
#define NPRE 512                // tail pre blocks

__device__ __align__(16) float g_pvec[BATCH * NCH * HDIM];  // 2 MB
__device__ __align__(16) float g_psum[BATCH * NCH];
__device__ __align__(16) float g_pre0[BATCH * 512];
__device__ __align__(16) float g_pre1[BATCH * 512];

__device__ __forceinline__ float warp_sum(float p) {
    #pragma unroll
    for (int o = 16; o > 0; o >>= 1) p += __shfl_down_sync(0xffffffffu, p, o);
    return p;
}

__device__ __forceinline__ float sigmoidf_(float x) {
    return 1.0f / (1.0f + expf(-x));
}

__device__ __forceinline__ float dot4(float4 a, float4 b) {
    return a.x * b.x + a.y * b.y + a.z * b.z + a.w * b.w;
}

__device__ __forceinline__ void cp16(void* smem_dst, const void* gmem_src) {
    unsigned int s = (unsigned int)__cvta_generic_to_shared(smem_dst);
    asm volatile("cp.async.cg.shared.global [%0], [%1], 16;" :: "r"(s), "l"(gmem_src));
}
#define CP_COMMIT() asm volatile("cp.async.commit_group;")
#define CP_WAIT(n)  asm volatile("cp.async.wait_group %0;" :: "n"(n))

// score 32 rows (base..base+31): 8 warps x 4 rows, interleaved shfl chains
__device__ __forceinline__ void score_rows4(
    const float* tile, float4 wv, float bias, float* s_sh,
    int base, int wrp, int lane)
{
    float acc[4];
    #pragma unroll
    for (int t = 0; t < 4; t++) {
        const float4 rv = *(const float4*)&tile[(base + wrp + 8 * t) * HDIM + lane * 4];
        acc[t] = dot4(rv, wv);
    }
    #pragma unroll
    for (int o = 16; o > 0; o >>= 1) {
        #pragma unroll
        for (int t = 0; t < 4; t++)
            acc[t] += __shfl_down_sync(0xffffffffu, acc[t], o);
    }
    if (lane == 0) {
        #pragma unroll
        for (int t = 0; t < 4; t++)
            s_sh[base + wrp + 8 * t] = acc[t] + bias;
    }
}

// ---------------------------------------------------------------------------
// Attention (+ tail pre): blocks [0,NATT) = 64-row cp.async tiles (32 KB,
// ~6 blocks/SM); blocks >= NATT = hh-gate precompute in the drain wave.
// ---------------------------------------------------------------------------
__global__ void __launch_bounds__(256) attn_pre_kernel(
    const float* __restrict__ enc,
    const float* __restrict__ h0,
    const float* __restrict__ c0,
    const float* __restrict__ attW,
    const float* __restrict__ attb,
    const float* __restrict__ W_hh0,
    const float* __restrict__ b_ih0, const float* __restrict__ b_hh0,
    const float* __restrict__ W_hh1,
    const float* __restrict__ b_ih1, const float* __restrict__ b_hh1)
{
    const int tid  = threadIdx.x;
    const int lane = tid & 31;
    const int wrp  = tid >> 5;

    if (blockIdx.x >= NATT) {
        const int p  = blockIdx.x - NATT;
        const int b  = p >> 3;
        const int k0 = (p & 7) * 64;
        const float4 hv0 = ((const float4*)(h0 + b * HDIM))[lane];
        const float4 hv1 = ((const float4*)(h0 + BATCH * HDIM + b * HDIM))[lane];
        #pragma unroll 4
        for (int t = 0; t < 8; t++) {
            const int k = k0 + wrp * 8 + t;
            float p0 = dot4(((const float4*)(W_hh0 + k * HDIM))[lane], hv0);
            p0 = warp_sum(p0);
            if (lane == 0) g_pre0[b * 512 + k] = p0 + b_ih0[k] + b_hh0[k];
        }
        #pragma unroll 4
        for (int t = 0; t < 8; t++) {
            const int k = k0 + wrp * 8 + t;
            float p1 = dot4(((const float4*)(W_hh1 + k * HDIM))[lane], hv1);
            p1 = warp_sum(p1);
            if (lane == 0) g_pre1[b * 512 + k] = p1 + b_ih1[k] + b_hh1[k];
        }
        return;
    }

    extern __shared__ __align__(16) float tile[];   // 64*128 floats = 32 KB

    __shared__ float s_sh[CHUNK];
    __shared__ float e_sh[CHUNK];
    __shared__ float red[4];
    __shared__ float bias_sh;
    __shared__ float sprev_sh;
    __shared__ float part2[2][HDIM];

    const int chunk = blockIdx.x & (NCH - 1);
    const int b     = blockIdx.x >> 6;
    const int start = chunk * CHUNK;

    // Stage tile: 2048 float4, 8 per thread, 2 commit groups (rows 0-31 / 32-63)
    {
        const float4* src = (const float4*)(enc + ((size_t)b * WTOT + start) * HDIM);
        float4* dst = (float4*)tile;
        #pragma unroll
        for (int i = 0; i < 4; i++) cp16(&dst[tid + 256 * i], &src[tid + 256 * i]);
        CP_COMMIT();
        #pragma unroll
        for (int i = 4; i < 8; i++) cp16(&dst[tid + 256 * i], &src[tid + 256 * i]);
        CP_COMMIT();
    }

    float4 vprev = make_float4(0.f, 0.f, 0.f, 0.f);
    if (wrp == 0 && start > 0)
        vprev = ((const float4*)(enc + ((size_t)b * WTOT + start - 1) * HDIM))[lane];
    const float4 wv = ((const float4*)attW)[lane];

    // Bias compute overlaps the transfers.
    if (tid < HDIM) {
        float p = h0[BATCH * HDIM + b * HDIM + tid]
                * c0[BATCH * HDIM + b * HDIM + tid]
                * attW[HDIM + tid];
        p = warp_sum(p);
        if (lane == 0) red[wrp] = p;
    }
    __syncthreads();
    if (tid == 0) bias_sh = red[0] + red[1] + red[2] + red[3] + attb[0];

    CP_WAIT(1);
    __syncthreads();              // rows 0..31 + bias visible
    const float bias = bias_sh;

    score_rows4(tile, wv, bias, s_sh, 0, wrp, lane);
    if (wrp == 0 && start > 0) {
        float s = warp_sum(dot4(vprev, wv));
        if (lane == 0) sprev_sh = s + bias;
    }

    CP_WAIT(0);
    __syncthreads();              // rows 32..63 visible
    score_rows4(tile, wv, bias, s_sh, 32, wrp, lane);
    __syncthreads();

    if (tid < CHUNK) {
        float logit;
        if (tid == 0) logit = (start == 0) ? 0.0f : sprev_sh;
        else          logit = s_sh[tid - 1];
        e_sh[tid] = expf(logit);
    }
    __syncthreads();

    // Weighted partial sum: 2 row-groups x 128 h-columns, 32 rows each.
    {
        const int h = tid & 127, grp = tid >> 7;
        float acc = 0.0f;
        #pragma unroll
        for (int j = 0; j < 32; j++) {
            const int r = grp * 32 + j;
            acc += e_sh[r] * tile[r * HDIM + h];
        }
        part2[grp][h] = acc;
    }
    __syncthreads();
    if (tid < HDIM)
        g_pvec[((size_t)b * NCH + chunk) * HDIM + tid] = part2[0][tid] + part2[1][tid];
    if (wrp == 0) {
        float es = e_sh[lane] + e_sh[lane + 32];
        es = warp_sum(es);
        if (lane == 0) g_psum[b * NCH + chunk] = es;
    }
}

// ---------------------------------------------------------------------------
// Pipelined coalesced warp-dots: 16 gates per warp, K=128.
// ---------------------------------------------------------------------------
__device__ __forceinline__ void lstm_gates(
    const float* __restrict__ W, const float4 xv,
    const float* __restrict__ pre_sh, float* gate_sh,
    int wrp, int lane)
{
    const int kbase = wrp * 16;
    float4 w[2][4];
    #pragma unroll
    for (int t = 0; t < 4; t++)
        w[0][t] = ((const float4*)(W + (kbase + t) * HDIM))[lane];
    #pragma unroll
    for (int g = 0; g < 4; g++) {
        if (g < 3) {
            #pragma unroll
            for (int t = 0; t < 4; t++)
                w[(g + 1) & 1][t] =
                    ((const float4*)(W + (kbase + (g + 1) * 4 + t) * HDIM))[lane];
        }
        float acc[4];
        #pragma unroll
        for (int t = 0; t < 4; t++) acc[t] = dot4(w[g & 1][t], xv);
        #pragma unroll
        for (int o = 16; o > 0; o >>= 1) {
            #pragma unroll
            for (int t = 0; t < 4; t++)
                acc[t] += __shfl_down_sync(0xffffffffu, acc[t], o);
        }
        if (lane == 0) {
            #pragma unroll
            for (int t = 0; t < 4; t++) {
                const int k = kbase + g * 4 + t;
                gate_sh[k] = acc[t] + pre_sh[k];
            }
        }
    }
}

// ---------------------------------------------------------------------------
// Decode (exact R9 structure): one block per batch, 1024 threads.
// ---------------------------------------------------------------------------
__global__ void __launch_bounds__(1024) decode_kernel(
    const float* __restrict__ input,
    const float* __restrict__ c0,
    const float* __restrict__ inp_W, const float* __restrict__ inp_b,
    const float* __restrict__ W_ih0,
    const float* __restrict__ W_ih1,
    float* __restrict__ out)
{
    __shared__ __align__(16) float cat_sh[256];
    __shared__ __align__(16) float xin_sh[HDIM];
    __shared__ __align__(16) float h1_sh[HDIM];
    __shared__ float gate_sh[512];
    __shared__ float c0_sh[2 * HDIM];
    __shared__ float vred[8][HDIM];
    __shared__ float sarr[NCH];
    __shared__ float pre0_sh[512];
    __shared__ float pre1_sh[512];
    __shared__ float S_sh;

    const int b = blockIdx.x;
    const int tid = threadIdx.x, lane = tid & 31, wrp = tid >> 5;

    // Early independent loads
    if (tid < HDIM) {
        c0_sh[tid]        = c0[b * HDIM + tid];
        c0_sh[HDIM + tid] = c0[BATCH * HDIM + b * HDIM + tid];
    }
    if (tid < 512) pre0_sh[tid] = g_pre0[b * 512 + tid];
    else           pre1_sh[tid - 512] = g_pre1[b * 512 + (tid - 512)];

    // Stage 0: reduce attention partials — 8 groups x 8 chunks, all 1024
    // threads write DISTINCT vred cells (no race).
    if (tid < NCH) sarr[tid] = g_psum[b * NCH + tid];
    {
        const int h = tid & 127, grp = tid >> 7;   // grp 0..7
        float v = 0.0f;
        #pragma unroll
        for (int c = 0; c < 8; c++)
            v += g_pvec[((size_t)b * NCH + grp * 8 + c) * HDIM + h];
        vred[grp][h] = v;
    }
    __syncthreads();
    float vcol = 0.0f;
    if (tid < HDIM) {
        #pragma unroll
        for (int g = 0; g < 8; g++) vcol += vred[g][tid];
    }
    if (wrp == 0) {
        float s = sarr[lane] + sarr[lane + 32];
        s = warp_sum(s);
        if (lane == 0) S_sh = s;
    }
    __syncthreads();
    if (tid < HDIM) {
        cat_sh[tid]        = vcol / S_sh;
        cat_sh[HDIM + tid] = input[b * HDIM + tid];
    }
    __syncthreads();

    // xin: 32 warps x 4 outputs, K=256. Prefetch weights then 4 chains.
    {
        const float4 c0v = ((const float4*)cat_sh)[lane];
        const float4 c1v = ((const float4*)cat_sh)[lane + 32];
        float4 a0[4], a1[4];
        #pragma unroll
        for (int t = 0; t < 4; t++) {
            const float4* wrow = (const float4*)(inp_W + (wrp * 4 + t) * 256);
            a0[t] = wrow[lane];
            a1[t] = wrow[lane + 32];
        }
        float acc[4];
        #pragma unroll
        for (int t = 0; t < 4; t++)
            acc[t] = dot4(a0[t], c0v) + dot4(a1[t], c1v);
        #pragma unroll
        for (int o = 16; o > 0; o >>= 1) {
            #pragma unroll
            for (int t = 0; t < 4; t++)
                acc[t] += __shfl_down_sync(0xffffffffu, acc[t], o);
        }
        if (lane == 0) {
            #pragma unroll
            for (int t = 0; t < 4; t++) {
                const int i = wrp * 4 + t;
                xin_sh[i] = acc[t] + inp_b[i];
            }
        }
    }
    __syncthreads();

    float* out_h1 = out + 8192 + b * HDIM;
    float* out_h2 = out + 16384 + b * HDIM;
    float* out_c1 = out + 24576 + b * HDIM;
    float* out_c2 = out + 32768 + b * HDIM;
    float* out_y  = out + b * HDIM;

    // LSTM layer 0
    lstm_gates(W_ih0, ((const float4*)xin_sh)[lane], pre0_sh, gate_sh, wrp, lane);
    __syncthreads();
    if (tid < HDIM) {
        const float ig = gate_sh[tid];
        const float fg = gate_sh[128 + tid];
        const float gg = gate_sh[256 + tid];
        const float og = gate_sh[384 + tid];
        const float cn = sigmoidf_(fg) * c0_sh[tid] + sigmoidf_(ig) * tanhf(gg);
        const float hn = sigmoidf_(og) * tanhf(cn);
        h1_sh[tid]  = hn;
        out_c1[tid] = cn;
        out_h1[tid] = hn;
    }
    __syncthreads();

    // LSTM layer 1
    lstm_gates(W_ih1, ((const float4*)h1_sh)[lane], pre1_sh, gate_sh, wrp, lane);
    __syncthreads();
    if (tid < HDIM) {
        const float ig = gate_sh[tid];
        const float fg = gate_sh[128 + tid];
        const float gg = gate_sh[256 + tid];
        const float og = gate_sh[384 + tid];
        const float cn = sigmoidf_(fg) * c0_sh[HDIM + tid] + sigmoidf_(ig) * tanhf(gg);
        const float hn = sigmoidf_(og) * tanhf(cn);
        out_c2[tid] = cn;
        out_h2[tid] = hn;
        out_y[tid]  = hn;
    }
}

extern "C" void kernel_launch(void* const* d_in, const int* in_sizes, int n_in,
                              void* d_out, int out_size)
{
    const float* input  = (const float*)d_in[0];
    const float* h0     = (const float*)d_in[1];
    const float* c0     = (const float*)d_in[2];
    const float* enc    = (const float*)d_in[3];
    const float* attW   = (const float*)d_in[4];
    const float* attb   = (const float*)d_in[5];
    const float* inp_W  = (const float*)d_in[6];
    const float* inp_b  = (const float*)d_in[7];
    const float* W_ih0  = (const float*)d_in[8];
    const float* W_hh0  = (const float*)d_in[9];
    const float* b_ih0  = (const float*)d_in[10];
    const float* b_hh0  = (const float*)d_in[11];
    const float* W_ih1  = (const float*)d_in[12];
    const float* W_hh1  = (const float*)d_in[13];
    const float* b_ih1  = (const float*)d_in[14];
    const float* b_hh1  = (const float*)d_in[15];
    float* out = (float*)d_out;

    const int tile_bytes = CHUNK * HDIM * sizeof(float);   // 32 KB
    cudaFuncSetAttribute(attn_pre_kernel,
                         cudaFuncAttributeMaxDynamicSharedMemorySize, tile_bytes);

    attn_pre_kernel<<<NATT + NPRE, 256, tile_bytes>>>(
        enc, h0, c0, attW, attb,
        W_hh0, b_ih0, b_hh0, W_hh1, b_ih1, b_hh1);
    decode_kernel<<<BATCH, 1024>>>(input, c0, inp_W, inp_b, W_ih0, W_ih1, out);
}